// round 5
// baseline (speedup 1.0000x reference)
#include <cuda_runtime.h>
#include <cuda_bf16.h>
#include <cstdint>

#define D      256
#define MAXN   8192
#define BM     128
#define BN     128
#define CSPLIT 2
#define NT     ((MAXN / CSPLIT) / BN)   // 32 tiles per CTA
#define LOG2E_OVER_T 28.853900817779268f
#define INV_T        20.0f

// SMEM layout (bytes)
#define SM_PART 0                       // 4 x 128 floats = 2048
#define SM_A    2048                    // 128 x 256 int8 = 32768 (swizzled)
#define SM_B0   (SM_A + 32768)          // 34816 (1024-aligned)
#define BUFSTRIDE 33792                 // 32768 B tile + 512 v + pad
#define SM_VOFF 32768                   // v floats at end of each B buffer
#define SM_TOTAL (SM_B0 + 2 * BUFSTRIDE)   // 102400

// ---------------- scratch -------------------------------------------------
__device__ __align__(16) int8_t g_a8[MAXN * D];
__device__ __align__(16) int8_t g_b8[MAXN * D];
__device__ float g_u[MAXN];             // LOG2E_OVER_T * ia * amax_a / 127
__device__ float g_v[MAXN];             // ib * amax_b / 127
__device__ float g_diag[MAXN];          // exact fp32 diagonal (natural units)
__device__ float g_part[MAXN * CSPLIT];

// ---------------- helpers --------------------------------------------------
__device__ __forceinline__ uint32_t smem_u32(const void* p) {
    return (uint32_t)__cvta_generic_to_shared(p);
}
__device__ __forceinline__ void cp_async16(uint32_t sdst, const void* gsrc) {
    asm volatile("cp.async.cg.shared.global [%0], [%1], 16;\n" :: "r"(sdst), "l"(gsrc));
}
#define CP_COMMIT() asm volatile("cp.async.commit_group;\n" ::: "memory")
#define CP_WAIT1()  asm volatile("cp.async.wait_group 1;\n" ::: "memory")

__device__ __forceinline__ float ex2f(float x) {
    float y; asm("ex2.approx.f32 %0, %1;" : "=f"(y) : "f"(x)); return y;
}
__device__ __forceinline__ void ldsm_x4(uint32_t r[4], uint32_t addr) {
    asm volatile("ldmatrix.sync.aligned.m8n8.x4.shared.b16 {%0,%1,%2,%3}, [%4];"
                 : "=r"(r[0]), "=r"(r[1]), "=r"(r[2]), "=r"(r[3]) : "r"(addr));
}
__device__ __forceinline__ void imma_s8(int c[4], const uint32_t a[4],
                                        uint32_t b0, uint32_t b1) {
    asm volatile(
        "mma.sync.aligned.m16n8k32.row.col.s32.s8.s8.s32 "
        "{%0,%1,%2,%3}, {%4,%5,%6,%7}, {%8,%9}, {%0,%1,%2,%3};\n"
        : "+r"(c[0]), "+r"(c[1]), "+r"(c[2]), "+r"(c[3])
        : "r"(a[0]), "r"(a[1]), "r"(a[2]), "r"(a[3]), "r"(b0), "r"(b1));
}
__device__ __forceinline__ uint32_t pack4_s8(int i0, int i1, int i2, int i3) {
    uint32_t t, r; uint32_t z = 0;
    asm("cvt.pack.sat.s8.s32.b32 %0, %1, %2, %3;" : "=r"(t) : "r"(i3), "r"(i2), "r"(z));
    asm("cvt.pack.sat.s8.s32.b32 %0, %1, %2, %3;" : "=r"(r) : "r"(i1), "r"(i0), "r"(t));
    return r;   // bytes LE: i0,i1,i2,i3
}

// load 128x256 int8 tile (32KB), XOR-swizzled 16B chunks; 256 threads, 8 passes
__device__ __forceinline__ void load_tile8(uint32_t sdst, const int8_t* g, int tid) {
    int c = tid & 15, rr = tid >> 4;
    #pragma unroll
    for (int p = 0; p < 8; p++) {
        int r = p * 16 + rr;
        uint32_t sw = (uint32_t)((c & 8) | ((c ^ r) & 7)) << 4;
        cp_async16(sdst + r * 256 + sw, g + (size_t)r * 256 + c * 16);
    }
}

// ---------------- kernel 1: norm + quantize + exact diagonal ----------------
__global__ void norm_kernel(const float4* __restrict__ a4, const float4* __restrict__ b4) {
    int w = threadIdx.x >> 5, lane = threadIdx.x & 31;
    int row0 = blockIdx.x * 16 + w * 2;

    #pragma unroll
    for (int rr = 0; rr < 2; rr++) {
        int row = row0 + rr;
        const float4* ar = a4 + (size_t)row * (D / 4);
        const float4* br = b4 + (size_t)row * (D / 4);
        float4 a0 = ar[lane * 2], a1 = ar[lane * 2 + 1];
        float4 b0 = br[lane * 2], b1 = br[lane * 2 + 1];

        float sa = a0.x*a0.x + a0.y*a0.y + a0.z*a0.z + a0.w*a0.w
                 + a1.x*a1.x + a1.y*a1.y + a1.z*a1.z + a1.w*a1.w;
        float sb = b0.x*b0.x + b0.y*b0.y + b0.z*b0.z + b0.w*b0.w
                 + b1.x*b1.x + b1.y*b1.y + b1.z*b1.z + b1.w*b1.w;
        float sd = a0.x*b0.x + a0.y*b0.y + a0.z*b0.z + a0.w*b0.w
                 + a1.x*b1.x + a1.y*b1.y + a1.z*b1.z + a1.w*b1.w;
        float ma = fmaxf(fmaxf(fmaxf(fabsf(a0.x), fabsf(a0.y)), fmaxf(fabsf(a0.z), fabsf(a0.w))),
                         fmaxf(fmaxf(fabsf(a1.x), fabsf(a1.y)), fmaxf(fabsf(a1.z), fabsf(a1.w))));
        float mb = fmaxf(fmaxf(fmaxf(fabsf(b0.x), fabsf(b0.y)), fmaxf(fabsf(b0.z), fabsf(b0.w))),
                         fmaxf(fmaxf(fabsf(b1.x), fabsf(b1.y)), fmaxf(fabsf(b1.z), fabsf(b1.w))));
        #pragma unroll
        for (int o = 16; o; o >>= 1) {
            sa += __shfl_xor_sync(0xffffffffu, sa, o);
            sb += __shfl_xor_sync(0xffffffffu, sb, o);
            sd += __shfl_xor_sync(0xffffffffu, sd, o);
            ma = fmaxf(ma, __shfl_xor_sync(0xffffffffu, ma, o));
            mb = fmaxf(mb, __shfl_xor_sync(0xffffffffu, mb, o));
        }
        float ia = rsqrtf(fmaxf(sa, 1e-16f));
        float ib = rsqrtf(fmaxf(sb, 1e-16f));
        ma = fmaxf(ma, 1e-12f);
        mb = fmaxf(mb, 1e-12f);
        float qa = 127.f / ma, qb = 127.f / mb;

        if (lane == 0) {
            g_diag[row] = sd * ia * ib * INV_T;
            g_u[row] = ia * ma * (LOG2E_OVER_T / 127.f);
            g_v[row] = ib * mb * (1.f / 127.f);
        }
        uint2 pa, pb;
        pa.x = pack4_s8(__float2int_rn(a0.x*qa), __float2int_rn(a0.y*qa),
                        __float2int_rn(a0.z*qa), __float2int_rn(a0.w*qa));
        pa.y = pack4_s8(__float2int_rn(a1.x*qa), __float2int_rn(a1.y*qa),
                        __float2int_rn(a1.z*qa), __float2int_rn(a1.w*qa));
        pb.x = pack4_s8(__float2int_rn(b0.x*qb), __float2int_rn(b0.y*qb),
                        __float2int_rn(b0.z*qb), __float2int_rn(b0.w*qb));
        pb.y = pack4_s8(__float2int_rn(b1.x*qb), __float2int_rn(b1.y*qb),
                        __float2int_rn(b1.z*qb), __float2int_rn(b1.w*qb));
        *(uint2*)(g_a8 + (size_t)row * D + lane * 8) = pa;
        *(uint2*)(g_b8 + (size_t)row * D + lane * 8) = pb;
    }
}

// ---------------- kernel 2: int8 IMMA GEMM + ex2 row-sum -------------------
// 256 threads = 8 warps, 2x4 warp grid, 64x32 warp tile, CTA tile 128x128.
__global__ __launch_bounds__(256, 1) void sim_lse_kernel() {
    extern __shared__ char sm[];
    uint32_t sbase = smem_u32(sm);
    int tid = threadIdx.x, w = tid >> 5, lane = tid & 31;
    int rb = blockIdx.x >> 1, cs = blockIdx.x & 1;
    int rowBase = rb * BM;
    int col0 = cs * (MAXN / CSPLIT);

    int wr = (w & 1) * 64;          // warp row offset (0/64)
    int wc = (w >> 1) * 32;         // warp col offset (0/32/64/96)
    int g2 = lane >> 3, l3 = lane & 7;
    int khA = g2 >> 1;              // A: groups 0,1 -> rows; 2,3 -> k-half
    int khB = g2 & 1;               // B: groups 0,1 -> n0-7;  k-half alternates

    // ldmatrix row base addresses
    // A matrices: m0=(r0-7,kLo) m1=(r8-15,kLo) m2=(r0-7,kHi) m3=(r8-15,kHi)
    uint32_t aAddr[4];
    #pragma unroll
    for (int mt = 0; mt < 4; mt++)
        aAddr[mt] = sbase + SM_A + (wr + mt * 16 + (g2 & 1) * 8 + l3) * 256;
    // B matrices: m0=(n0-7,kLo) m1=(n0-7,kHi) m2=(n8-15,kLo) m3=(n8-15,kHi)
    uint32_t bOff[2];
    #pragma unroll
    for (int bt = 0; bt < 2; bt++)
        bOff[bt] = (uint32_t)((wc + bt * 16 + (g2 >> 1) * 8 + l3) * 256);

    // per-thread row scales u (8 rows)
    float u0[4], u1[4];
    #pragma unroll
    for (int mt = 0; mt < 4; mt++) {
        u0[mt] = g_u[rowBase + wr + mt * 16 + (lane >> 2)];
        u1[mt] = g_u[rowBase + wr + mt * 16 + 8 + (lane >> 2)];
    }

    // prologue: A tile + B tile 0 + v slice 0
    load_tile8(sbase + SM_A,  g_a8 + (size_t)rowBase * D, tid);
    load_tile8(sbase + SM_B0, g_b8 + (size_t)col0 * D,    tid);
    if (tid < 32) cp_async16(sbase + SM_B0 + SM_VOFF + tid * 16, g_v + col0 + tid * 4);
    CP_COMMIT();

    int acc[4][4][4];
    #pragma unroll
    for (int mt = 0; mt < 4; mt++)
        #pragma unroll
        for (int j = 0; j < 4; j++)
            acc[mt][j][0] = acc[mt][j][1] = acc[mt][j][2] = acc[mt][j][3] = 0;
    float rs[4][2] = {};

    for (int t = 0; t < NT; t++) {
        __syncthreads();            // all reads of buf[(t+1)&1] (iter t-1) done
        if (t + 1 < NT) {
            uint32_t nb = sbase + SM_B0 + ((t + 1) & 1) * BUFSTRIDE;
            load_tile8(nb, g_b8 + (size_t)(col0 + (t + 1) * BN) * D, tid);
            if (tid < 32)
                cp_async16(nb + SM_VOFF + tid * 16, g_v + col0 + (t + 1) * BN + tid * 4);
        }
        CP_COMMIT();                // empty group on last iter keeps wait_group 1 valid
        CP_WAIT1();
        __syncthreads();

        uint32_t bbuf = sbase + SM_B0 + (t & 1) * BUFSTRIDE;

        #pragma unroll
        for (int kk = 0; kk < 8; kk++) {
            int cA = kk * 2 + khA, cB = kk * 2 + khB;
            uint32_t swA = (uint32_t)((cA & 8) | ((cA ^ l3) & 7)) << 4;
            uint32_t swB = (uint32_t)((cB & 8) | ((cB ^ l3) & 7)) << 4;
            uint32_t af[4][4], bf[2][4];
            #pragma unroll
            for (int mt = 0; mt < 4; mt++) ldsm_x4(af[mt], aAddr[mt] + swA);
            #pragma unroll
            for (int bt = 0; bt < 2; bt++) ldsm_x4(bf[bt], bbuf + bOff[bt] + swB);
            #pragma unroll
            for (int mt = 0; mt < 4; mt++) {
                #pragma unroll
                for (int bt = 0; bt < 2; bt++) {
                    imma_s8(acc[mt][bt * 2],     af[mt], bf[bt][0], bf[bt][1]);
                    imma_s8(acc[mt][bt * 2 + 1], af[mt], bf[bt][2], bf[bt][3]);
                }
            }
        }

        // epilogue: l2 = acc * u_i * v_j (log2 units), sum 2^l2
        const float* vp = (const float*)(sm + SM_B0 + (t & 1) * BUFSTRIDE + SM_VOFF);
        float2 vv[4];
        #pragma unroll
        for (int j = 0; j < 4; j++)
            vv[j] = *(const float2*)(vp + wc + j * 8 + (lane & 3) * 2);
        #pragma unroll
        for (int mt = 0; mt < 4; mt++) {
            #pragma unroll
            for (int j = 0; j < 4; j++) {
                float f0 = __int2float_rn(acc[mt][j][0]) * u0[mt];
                float f1 = __int2float_rn(acc[mt][j][1]) * u0[mt];
                float f2 = __int2float_rn(acc[mt][j][2]) * u1[mt];
                float f3 = __int2float_rn(acc[mt][j][3]) * u1[mt];
                rs[mt][0] += ex2f(f0 * vv[j].x) + ex2f(f1 * vv[j].y);
                rs[mt][1] += ex2f(f2 * vv[j].x) + ex2f(f3 * vv[j].y);
                acc[mt][j][0] = acc[mt][j][1] = acc[mt][j][2] = acc[mt][j][3] = 0;
            }
        }
    }

    // reduce 4 lanes sharing each row, then across the 4 warp-columns via smem
    float* partial = (float*)(sm + SM_PART);
    #pragma unroll
    for (int mt = 0; mt < 4; mt++) {
        #pragma unroll
        for (int h = 0; h < 2; h++) {
            float r = rs[mt][h];
            r += __shfl_xor_sync(0xffffffffu, r, 1);
            r += __shfl_xor_sync(0xffffffffu, r, 2);
            if ((lane & 3) == 0)
                partial[(w >> 1) * 128 + wr + mt * 16 + h * 8 + (lane >> 2)] = r;
        }
    }
    __syncthreads();
    if (tid < 128) {
        float s = partial[tid] + partial[128 + tid] + partial[256 + tid] + partial[384 + tid];
        g_part[(size_t)(rowBase + tid) * CSPLIT + cs] = s;
    }
}

// ---------------- kernel 3: final loss ------------------------------------
__global__ void reduce_kernel(float* __restrict__ out, int N) {
    __shared__ float s[256];
    int t = threadIdx.x;
    float acc = 0.f;
    for (int i = t; i < N; i += 256) {
        float sum2 = g_part[i * CSPLIT] + g_part[i * CSPLIT + 1];
        acc += __logf(sum2) - g_diag[i];      // log(sum 2^l2) = LSE (natural units)
    }
    s[t] = acc;
    __syncthreads();
    for (int o = 128; o; o >>= 1) {
        if (t < o) s[t] += s[t + o];
        __syncthreads();
    }
    if (t == 0) out[0] = s[0] / (float)N;
}

// ---------------- launch ---------------------------------------------------
extern "C" void kernel_launch(void* const* d_in, const int* in_sizes, int n_in,
                              void* d_out, int out_size) {
    const float* a = (const float*)d_in[0];
    const float* b = (const float*)d_in[1];
    int N = in_sizes[0] / D;   // 8192

    cudaFuncSetAttribute(sim_lse_kernel,
                         cudaFuncAttributeMaxDynamicSharedMemorySize, SM_TOTAL);

    norm_kernel<<<N / 16, 256>>>((const float4*)a, (const float4*)b);
    sim_lse_kernel<<<(N / BM) * CSPLIT, 256, SM_TOTAL>>>();
    reduce_kernel<<<1, 256>>>((float*)d_out, N);
}

// round 6
// speedup vs baseline: 2.8513x; 2.8513x over previous
#include <cuda_runtime.h>
#include <cuda_bf16.h>
#include <cstdint>

#define D      256
#define MAXN   8192
#define BM     128                 // rows per CTA
#define BN     128                 // cols per tile
#define CSPLIT 2                   // column splits
#define NT     ((MAXN / CSPLIT) / BN)   // 32 tiles per CTA
#define LOG2E_OVER_T 28.853900817779268f
#define INV_T        20.0f

// SMEM layout (bytes)
#define SM_PART 0                  // 2 x 128 floats
#define SM_A    2048               // 128 rows x 512 B (swizzled)  = 65536
#define SM_B0   (SM_A + 65536)
#define SM_TOTAL (SM_B0 + 2 * 65536)   // 198656

// ---------------- scratch -------------------------------------------------
__device__ __align__(16) __nv_bfloat16 g_a[MAXN * D];
__device__ __align__(16) __nv_bfloat16 g_b[MAXN * D];
__device__ float g_diag[MAXN];
__device__ float g_part[MAXN * CSPLIT];

// ---------------- helpers --------------------------------------------------
__device__ __forceinline__ uint32_t smem_u32(const void* p) {
    return (uint32_t)__cvta_generic_to_shared(p);
}
__device__ __forceinline__ void cp_async16(uint32_t sdst, const void* gsrc) {
    asm volatile("cp.async.cg.shared.global [%0], [%1], 16;\n" :: "r"(sdst), "l"(gsrc));
}
#define CP_COMMIT() asm volatile("cp.async.commit_group;\n" ::: "memory")
#define CP_WAIT1()  asm volatile("cp.async.wait_group 1;\n" ::: "memory")

__device__ __forceinline__ float ex2f(float x) {
    float y; asm("ex2.approx.f32 %0, %1;" : "=f"(y) : "f"(x)); return y;
}
__device__ __forceinline__ void ldsm_x4(uint32_t r[4], uint32_t addr) {
    asm volatile("ldmatrix.sync.aligned.m8n8.x4.shared.b16 {%0,%1,%2,%3}, [%4];"
                 : "=r"(r[0]), "=r"(r[1]), "=r"(r[2]), "=r"(r[3]) : "r"(addr));
}
__device__ __forceinline__ void mma_bf16(float c[4], const uint32_t a[4],
                                         uint32_t b0, uint32_t b1) {
    asm volatile(
        "mma.sync.aligned.m16n8k16.row.col.f32.bf16.bf16.f32 "
        "{%0,%1,%2,%3}, {%4,%5,%6,%7}, {%8,%9}, {%0,%1,%2,%3};\n"
        : "+f"(c[0]), "+f"(c[1]), "+f"(c[2]), "+f"(c[3])
        : "r"(a[0]), "r"(a[1]), "r"(a[2]), "r"(a[3]), "r"(b0), "r"(b1));
}

// cp.async loader: 128x256 bf16 tile (64KB), XOR-swizzled 16B chunks, 256 threads
__device__ __forceinline__ void load_tile(uint32_t sdst_base,
                                          const __nv_bfloat16* gsrc, int tid) {
    int c = tid & 31, r8 = tid >> 5;            // chunk 0..31, row group 0..7
    #pragma unroll
    for (int p = 0; p < 16; p++) {
        int row = p * 8 + r8;
        uint32_t sdst = sdst_base + row * 512 + (((uint32_t)(c ^ (row & 7))) << 4);
        cp_async16(sdst, gsrc + (size_t)row * D + c * 8);
    }
}

// ---------------- kernel 1: norms + exact diagonal (warp per row) ----------
__global__ void norm_kernel(const float4* __restrict__ a4, const float4* __restrict__ b4) {
    int w = threadIdx.x >> 5, lane = threadIdx.x & 31;
    int row = blockIdx.x * 8 + w;
    const float4* ar = a4 + (size_t)row * (D / 4);
    const float4* br = b4 + (size_t)row * (D / 4);
    float4 a0 = ar[lane * 2], a1 = ar[lane * 2 + 1];
    float4 b0 = br[lane * 2], b1 = br[lane * 2 + 1];

    float sa = a0.x*a0.x + a0.y*a0.y + a0.z*a0.z + a0.w*a0.w
             + a1.x*a1.x + a1.y*a1.y + a1.z*a1.z + a1.w*a1.w;
    float sb = b0.x*b0.x + b0.y*b0.y + b0.z*b0.z + b0.w*b0.w
             + b1.x*b1.x + b1.y*b1.y + b1.z*b1.z + b1.w*b1.w;
    float sd = a0.x*b0.x + a0.y*b0.y + a0.z*b0.z + a0.w*b0.w
             + a1.x*b1.x + a1.y*b1.y + a1.z*b1.z + a1.w*b1.w;
    #pragma unroll
    for (int o = 16; o; o >>= 1) {
        sa += __shfl_xor_sync(0xffffffffu, sa, o);
        sb += __shfl_xor_sync(0xffffffffu, sb, o);
        sd += __shfl_xor_sync(0xffffffffu, sd, o);
    }
    float ia = rsqrtf(fmaxf(sa, 1e-16f));
    float ib = rsqrtf(fmaxf(sb, 1e-16f));
    if (lane == 0) g_diag[row] = sd * ia * ib * INV_T;

    float fa = ia * LOG2E_OVER_T;
    __nv_bfloat162 p0 = __floats2bfloat162_rn(a0.x*fa, a0.y*fa);
    __nv_bfloat162 p1 = __floats2bfloat162_rn(a0.z*fa, a0.w*fa);
    __nv_bfloat162 p2 = __floats2bfloat162_rn(a1.x*fa, a1.y*fa);
    __nv_bfloat162 p3 = __floats2bfloat162_rn(a1.z*fa, a1.w*fa);
    uint4 ua = { *(uint32_t*)&p0, *(uint32_t*)&p1, *(uint32_t*)&p2, *(uint32_t*)&p3 };
    *(uint4*)(g_a + (size_t)row * D + lane * 8) = ua;

    __nv_bfloat162 q0 = __floats2bfloat162_rn(b0.x*ib, b0.y*ib);
    __nv_bfloat162 q1 = __floats2bfloat162_rn(b0.z*ib, b0.w*ib);
    __nv_bfloat162 q2 = __floats2bfloat162_rn(b1.x*ib, b1.y*ib);
    __nv_bfloat162 q3 = __floats2bfloat162_rn(b1.z*ib, b1.w*ib);
    uint4 ub = { *(uint32_t*)&q0, *(uint32_t*)&q1, *(uint32_t*)&q2, *(uint32_t*)&q3 };
    *(uint4*)(g_b + (size_t)row * D + lane * 8) = ub;
}

// ---------------- kernel 2: ldmatrix + HMMA GEMM + ex2 row-sum -------------
// 256 threads = 8 warps, 4x2 warp grid, 32x64 warp tile, CTA tile 128x128.
// 2 warps per SMSP so epilogue/LDSM of one warp overlaps the other's MMA.
__global__ __launch_bounds__(256, 1) void sim_lse_kernel() {
    extern __shared__ char sm[];
    uint32_t sbase = smem_u32(sm);
    int tid = threadIdx.x, w = tid >> 5, lane = tid & 31;
    int rb = blockIdx.x >> 1, cs = blockIdx.x & 1;
    int rowBase = rb * BM;
    int col0 = cs * (MAXN / CSPLIT);

    int wr = (w & 3) * 32;        // warp row offset: 0/32/64/96
    int wc = (w >> 2) * 64;       // warp col offset: 0/64
    int g  = lane >> 3, l3 = lane & 7;
    uint32_t rk = (uint32_t)(l3 >> 1);       // XOR term for 32B k-chunk pair

    // ldmatrix base addresses (verified in R3: m0/m1 = rows, m2/m3 = k-high half)
    uint32_t abase[2], boff[4];
    {
        uint32_t c0a = (uint32_t)(((g >> 1) ^ (l3 & 1)) << 4);
        uint32_t c0b = (uint32_t)(((g & 1) ^ (l3 & 1)) << 4);
        #pragma unroll
        for (int mt = 0; mt < 2; mt++) {
            int row = wr + mt * 16 + (g & 1) * 8 + l3;
            abase[mt] = sbase + SM_A + row * 512 + c0a;
        }
        #pragma unroll
        for (int nt = 0; nt < 4; nt++) {
            int n = wc + nt * 16 + (g >> 1) * 8 + l3;
            boff[nt] = (uint32_t)(n * 512) + c0b;
        }
    }

    // prologue: A tile + B tile 0
    load_tile(sbase + SM_A,  g_a + (size_t)rowBase * D, tid);
    load_tile(sbase + SM_B0, g_b + (size_t)col0 * D,   tid);
    CP_COMMIT();

    float acc[2][8][4];
    #pragma unroll
    for (int mt = 0; mt < 2; mt++)
        #pragma unroll
        for (int j = 0; j < 8; j++)
            acc[mt][j][0] = acc[mt][j][1] = acc[mt][j][2] = acc[mt][j][3] = 0.f;
    float rs0[2] = {0, 0}, rs1[2] = {0, 0};

    for (int t = 0; t < NT; t++) {
        __syncthreads();           // all reads of buf[(t+1)&1] (iter t-1) done
        if (t + 1 < NT)
            load_tile(sbase + SM_B0 + ((t + 1) & 1) * 65536,
                      g_b + (size_t)(col0 + (t + 1) * BN) * D, tid);
        CP_COMMIT();               // empty group on last iter keeps wait_group 1 valid
        CP_WAIT1();                // group t retired -> buf[t&1] ready
        __syncthreads();

        uint32_t bbuf = sbase + SM_B0 + (t & 1) * 65536;

        #pragma unroll
        for (int kk = 0; kk < 16; kk++) {
            uint32_t koff = ((uint32_t)(kk ^ rk)) << 5;
            uint32_t af[2][4], bf[4][4];
            #pragma unroll
            for (int mt = 0; mt < 2; mt++) ldsm_x4(af[mt], abase[mt] + koff);
            #pragma unroll
            for (int nt = 0; nt < 4; nt++) ldsm_x4(bf[nt], bbuf + boff[nt] + koff);
            #pragma unroll
            for (int mt = 0; mt < 2; mt++) {
                #pragma unroll
                for (int nt = 0; nt < 4; nt++) {
                    mma_bf16(acc[mt][nt * 2],     af[mt], bf[nt][0], bf[nt][1]);
                    mma_bf16(acc[mt][nt * 2 + 1], af[mt], bf[nt][2], bf[nt][3]);
                }
            }
        }

        // epilogue: logits in log2 units, |x| <= 29 -> plain sum of 2^x
        #pragma unroll
        for (int mt = 0; mt < 2; mt++) {
            #pragma unroll
            for (int j = 0; j < 8; j++) {
                rs0[mt] += ex2f(acc[mt][j][0]) + ex2f(acc[mt][j][1]);
                rs1[mt] += ex2f(acc[mt][j][2]) + ex2f(acc[mt][j][3]);
                acc[mt][j][0] = acc[mt][j][1] = acc[mt][j][2] = acc[mt][j][3] = 0.f;
            }
        }
    }

    // reduce across 4 lanes sharing each row, then across the 2 warp-columns
    #pragma unroll
    for (int mt = 0; mt < 2; mt++) {
        rs0[mt] += __shfl_xor_sync(0xffffffffu, rs0[mt], 1);
        rs0[mt] += __shfl_xor_sync(0xffffffffu, rs0[mt], 2);
        rs1[mt] += __shfl_xor_sync(0xffffffffu, rs1[mt], 1);
        rs1[mt] += __shfl_xor_sync(0xffffffffu, rs1[mt], 2);
    }
    float* partial = (float*)(sm + SM_PART);
    if ((lane & 3) == 0) {
        int half = (w >> 2) * 128;
        #pragma unroll
        for (int mt = 0; mt < 2; mt++) {
            partial[half + wr + mt * 16 + (lane >> 2)]     = rs0[mt];
            partial[half + wr + mt * 16 + 8 + (lane >> 2)] = rs1[mt];
        }
    }
    __syncthreads();
    if (tid < 128)
        g_part[(size_t)(rowBase + tid) * CSPLIT + cs] = partial[tid] + partial[128 + tid];
}

// ---------------- kernel 3: final loss ------------------------------------
__global__ void reduce_kernel(float* __restrict__ out, int N) {
    __shared__ float s[256];
    int t = threadIdx.x;
    float acc = 0.f;
    for (int i = t; i < N; i += 256) {
        float sum2 = g_part[i * CSPLIT] + g_part[i * CSPLIT + 1];
        acc += __logf(sum2) - g_diag[i];       // log(sum 2^l2) = LSE (natural)
    }
    s[t] = acc;
    __syncthreads();
    for (int o = 128; o; o >>= 1) {
        if (t < o) s[t] += s[t + o];
        __syncthreads();
    }
    if (t == 0) out[0] = s[0] / (float)N;
}

// ---------------- launch ---------------------------------------------------
extern "C" void kernel_launch(void* const* d_in, const int* in_sizes, int n_in,
                              void* d_out, int out_size) {
    const float* a = (const float*)d_in[0];
    const float* b = (const float*)d_in[1];
    int N = in_sizes[0] / D;   // 8192

    cudaFuncSetAttribute(sim_lse_kernel,
                         cudaFuncAttributeMaxDynamicSharedMemorySize, SM_TOTAL);

    norm_kernel<<<N / 8, 256>>>((const float4*)a, (const float4*)b);
    sim_lse_kernel<<<(N / BM) * CSPLIT, 256, SM_TOTAL>>>();
    reduce_kernel<<<1, 256>>>((float*)d_out, N);
}